// round 1
// baseline (speedup 1.0000x reference)
#include <cuda_runtime.h>
#include <stdint.h>

#define BNUM 32
#define PNUM 8732
#define CFG  20          // foreground classes
#define NPAIR (BNUM*CFG) // 640
#define KPRE 256
#define TOPK 200
#define CAP  2048

// ------------------------------------------------------------------
// scratch (device globals: no allocation allowed)
// ------------------------------------------------------------------
__device__ float  g_probs[(size_t)BNUM * CFG * PNUM];  // [b][c][p]
__device__ float4 g_boxes[(size_t)BNUM * PNUM];        // decoded corner boxes

__device__ __forceinline__ uint32_t mono(float f) {
    uint32_t u = __float_as_uint(f);
    return (u & 0x80000000u) ? ~u : (u | 0x80000000u);
}

// ------------------------------------------------------------------
// kernel 1: softmax (exact jax.nn.softmax order) + decode
// ------------------------------------------------------------------
__global__ void prep_kernel(const float* __restrict__ loc,
                            const float* __restrict__ conf,
                            const float* __restrict__ prior) {
    int g = blockIdx.x * blockDim.x + threadIdx.x;
    if (g >= BNUM * PNUM) return;
    int b = g / PNUM, p = g % PNUM;

    const float* cp = conf + (size_t)g * 21;
    float x[21];
#pragma unroll
    for (int c = 0; c < 21; c++) x[c] = cp[c];
    float m = x[0];
#pragma unroll
    for (int c = 1; c < 21; c++) m = fmaxf(m, x[c]);
    float e[21];
    float s = 0.f;
#pragma unroll
    for (int c = 0; c < 21; c++) { e[c] = expf(x[c] - m); s += e[c]; }
#pragma unroll
    for (int c = 1; c < 21; c++)
        g_probs[((size_t)b * CFG + (c - 1)) * PNUM + p] = e[c] / s;

    float4 l  = ((const float4*)loc)[g];
    float4 pr = ((const float4*)prior)[p];
    // centers = p_xy + (loc_xy * 0.1) * p_wh ; wh = p_wh * exp(loc_wh * 0.2)
    float cx = pr.x + (l.x * 0.1f) * pr.z;
    float cy = pr.y + (l.y * 0.1f) * pr.w;
    float w  = pr.z * expf(l.z * 0.2f);
    float h  = pr.w * expf(l.w * 0.2f);
    float x1 = cx - w * 0.5f;
    float y1 = cy - h * 0.5f;
    g_boxes[g] = make_float4(x1, y1, x1 + w, y1 + h);
}

// ------------------------------------------------------------------
// kernel 2: per (b,c) pair — radix-select top-256 (stable by index),
// greedy NMS, emit top-200 rows (score,x1,y1,x2,y2)
// ------------------------------------------------------------------
__global__ __launch_bounds__(256) void topk_nms_kernel(float* __restrict__ out) {
    __shared__ uint32_t           s_hist[2048];
    __shared__ uint32_t           s_csum[256];
    __shared__ unsigned long long s_cand[CAP];
    __shared__ float4             s_box[KPRE];
    __shared__ float              s_score[KPRE];
    __shared__ float              s_area[KPRE];
    __shared__ uint32_t           s_keep[8];
    __shared__ uint32_t           s_wpre[8];
    __shared__ uint32_t           s_sel[3];
    __shared__ uint32_t           s_cnt;

    const int pair = blockIdx.x;
    const int b    = pair / CFG;
    const int tid  = threadIdx.x;
    const int wid  = tid >> 5, lane = tid & 31;
    const float* sc = g_probs + (size_t)pair * PNUM;

    // ---------- radix-select threshold F so that count(key >= F) in [256, CAP] ----------
    uint32_t F = 0, n_above = 0, M = 0;
    for (int level = 0; level < 3; level++) {
        for (int i = tid; i < 2048; i += 256) s_hist[i] = 0;
        __syncthreads();
        for (int p = tid; p < PNUM; p += 256) {
            uint32_t k = mono(sc[p]);
            bool part; uint32_t bin;
            if (level == 0)      { part = true;                            bin = k >> 21; }
            else if (level == 1) { part = ((k & 0xFFE00000u) == F);        bin = (k >> 10) & 0x7FFu; }
            else                 { part = ((k & 0xFFFFFC00u) == F);        bin = k & 0x3FFu; }
            if (part) atomicAdd(&s_hist[bin], 1u);
        }
        __syncthreads();
        uint32_t cs = 0;
#pragma unroll
        for (int i = 0; i < 8; i++) cs += s_hist[tid * 8 + i];
        s_csum[tid] = cs;
        __syncthreads();
        if (tid == 0) {
            uint32_t acc = n_above;
            int chunk = 0;
            for (int cg = 255; cg >= 0; cg--) {
                if (acc + s_csum[cg] >= KPRE) { chunk = cg; break; }
                acc += s_csum[cg];
            }
            int b1 = chunk * 8;
            for (int bi = chunk * 8 + 7; bi >= chunk * 8; bi--) {
                if (acc + s_hist[bi] >= KPRE) { b1 = bi; break; }
                acc += s_hist[bi];
            }
            s_sel[0] = (uint32_t)b1; s_sel[1] = acc; s_sel[2] = s_hist[b1];
        }
        __syncthreads();
        uint32_t b1 = s_sel[0]; n_above = s_sel[1]; uint32_t cntb = s_sel[2];
        if (level == 0)      F = b1 << 21;
        else if (level == 1) F |= b1 << 10;
        else                 F |= b1;
        M = n_above + cntb;
        if (M <= CAP || level == 2) break;
    }

    // ---------- gather candidates (key >= F), key64 = mono(score) | ~idx ----------
    if (tid == 0) s_cnt = 0;
    __syncthreads();
    for (int p = tid; p < PNUM; p += 256) {
        uint32_t k = mono(sc[p]);
        if (k >= F) {
            uint32_t pos = atomicAdd(&s_cnt, 1u);
            if (pos < CAP)
                s_cand[pos] = ((unsigned long long)k << 32) | (uint32_t)(~(uint32_t)p);
        }
    }
    __syncthreads();
    uint32_t Mg = s_cnt; if (Mg > CAP) Mg = CAP;
    uint32_t N = 256; while (N < Mg) N <<= 1;
    for (uint32_t i = Mg + tid; i < N; i += 256) s_cand[i] = 0ULL;
    __syncthreads();

    // ---------- bitonic sort descending (score desc, then index asc) ----------
    for (uint32_t kk = 2; kk <= N; kk <<= 1) {
        for (uint32_t j = kk >> 1; j > 0; j >>= 1) {
            for (uint32_t t = tid; t < N; t += 256) {
                uint32_t q = t ^ j;
                if (q > t) {
                    unsigned long long a = s_cand[t], c2 = s_cand[q];
                    bool keepLarger = ((t & kk) == 0);
                    if ((a < c2) == keepLarger) { s_cand[t] = c2; s_cand[q] = a; }
                }
            }
            __syncthreads();
        }
    }

    // ---------- extract top-256 ----------
    float4 bj; float aj; float scv;
    {
        unsigned long long key = s_cand[tid];
        uint32_t hi = (uint32_t)(key >> 32);
        uint32_t lo = (uint32_t)key;
        uint32_t idx = ~lo;
        if (idx >= PNUM) idx = 0;  // safety (pad keys only in pathological case)
        uint32_t ub = (hi & 0x80000000u) ? (hi ^ 0x80000000u) : ~hi;
        scv = __uint_as_float(ub);
        s_score[tid] = scv;
        bj = g_boxes[(size_t)b * PNUM + idx];
        s_box[tid] = bj;
        aj = fmaxf(bj.z - bj.x, 0.f) * fmaxf(bj.w - bj.y, 0.f);
        s_area[tid] = aj;
        bool valid = scv > 0.01f;
        uint32_t bal = __ballot_sync(0xFFFFFFFFu, valid);
        if (lane == 0) s_keep[wid] = bal;
    }
    __syncthreads();

    // ---------- greedy NMS scan (exact reference semantics, exact f32 division) ----------
    for (int i = 0; i < KPRE - 1; i++) {
        uint32_t kw = s_keep[i >> 5];
        if (kw & (1u << (i & 31))) {           // block-uniform branch
            bool sup = false;
            if (wid * 32 + 31 > i) {           // warp contains some j > i
                float4 bi = s_box[i];
                float wx = fmaxf(fminf(bi.z, bj.z) - fmaxf(bi.x, bj.x), 0.f);
                float wy = fmaxf(fminf(bi.w, bj.w) - fmaxf(bi.y, bj.y), 0.f);
                float inter = wx * wy;
                if (inter > 0.f && tid > i) {
                    float uni = s_area[i] + aj - inter;
                    float mu  = fmaxf(uni, 1e-9f);
                    sup = (inter / mu) > 0.45f;   // IEEE div, matches jnp
                }
            }
            uint32_t bal = __ballot_sync(0xFFFFFFFFu, sup);
            if (lane == 0 && bal) s_keep[wid] &= ~bal;
            __syncthreads();
        }
    }
    __syncthreads();

    // ---------- compaction + output ----------
    if (tid == 0) {
        uint32_t a = 0;
#pragma unroll
        for (int w2 = 0; w2 < 8; w2++) { s_wpre[w2] = a; a += __popc(s_keep[w2]); }
    }
    float* op = out + (size_t)pair * (TOPK * 5);
    for (int i = tid; i < TOPK * 5; i += 256) op[i] = 0.f;
    __syncthreads();

    uint32_t kwm = s_keep[wid];
    if ((kwm >> lane) & 1u) {
        uint32_t rank = s_wpre[wid] + __popc(kwm & ((1u << lane) - 1u));
        if (rank < TOPK) {
            float* r = op + (size_t)rank * 5;
            r[0] = scv;
            r[1] = bj.x; r[2] = bj.y; r[3] = bj.z; r[4] = bj.w;
        }
    }
}

// ------------------------------------------------------------------
extern "C" void kernel_launch(void* const* d_in, const int* in_sizes, int n_in,
                              void* d_out, int out_size) {
    const float* loc   = (const float*)d_in[0];
    const float* conf  = (const float*)d_in[1];
    const float* prior = (const float*)d_in[2];
    float* out = (float*)d_out;

    int total = BNUM * PNUM;
    prep_kernel<<<(total + 255) / 256, 256>>>(loc, conf, prior);
    topk_nms_kernel<<<NPAIR, 256>>>(out);
}